// round 1
// baseline (speedup 1.0000x reference)
#include <cuda_runtime.h>
#include <math_constants.h>
#include <cstdint>

#define EPS 1e-5f

// ---------------- scratch (static device globals; no allocation) ----------------
// B=8, C=256, C2=128, H=W=64, HW=4096, pooled HW=1024
__device__ float g_x1[8 * 128 * 4096];    // conv1 output, NCHW flat == X1 [4096,128] rm per batch
__device__ float g_y2[8 * 128 * 4096];    // conv2 output pre-pool
__device__ float g_x23[8 * 128 * 1024];   // pooled; == X2 [128,1024] and X3 [1024,128] views
__device__ float g_attn[8 * 128 * 4096];  // attention out [4096,128] rm == NCHW for conv3

// ---------------- 1x1 conv + BN + ReLU (+ optional residual) as tiled GEMM ----------------
// C[o,p] = relu((sum_c W[o,c]*X[c,p] + bias[o])*scale[o] + shift[o]) (+ resid)
// grid: (HW/64, O/64, B), block: 256 (16x16), BM=BN=64, BK=16, 4x4 microtile
__global__ __launch_bounds__(256) void conv_bn_relu_kernel(
    const float* __restrict__ X, const float* __restrict__ W,
    const float* __restrict__ bias, const float* __restrict__ gam,
    const float* __restrict__ beta, const float* __restrict__ mean,
    const float* __restrict__ var, const float* __restrict__ resid,
    float* __restrict__ Y, int K, int O, int HW)
{
    __shared__ float Ws[16][65];  // [k][o], pad 65 => conflict-free transposed stores
    __shared__ float Xs[16][64];  // [k][p]

    const int b  = blockIdx.z;
    const int o0 = blockIdx.y * 64;
    const int p0 = blockIdx.x * 64;
    const int tid = threadIdx.x;
    const int tx = tid & 15, ty = tid >> 4;

    const float* Xb = X + (size_t)b * K * HW;

    float acc[4][4];
#pragma unroll
    for (int i = 0; i < 4; i++)
#pragma unroll
        for (int j = 0; j < 4; j++) acc[i][j] = 0.f;

    for (int k0 = 0; k0 < K; k0 += 16) {
        {
            int kk = tid & 15, i = tid >> 4;
#pragma unroll
            for (int l = 0; l < 4; l++)
                Ws[kk][i + 16 * l] = W[(size_t)(o0 + i + 16 * l) * K + (k0 + kk)];
        }
        {
            int pp = tid & 63, kb = tid >> 6;
#pragma unroll
            for (int l = 0; l < 4; l++)
                Xs[kb + 4 * l][pp] = Xb[(size_t)(k0 + kb + 4 * l) * HW + (p0 + pp)];
        }
        __syncthreads();
#pragma unroll
        for (int kk = 0; kk < 16; kk++) {
            float a0 = Ws[kk][ty * 4 + 0];
            float a1 = Ws[kk][ty * 4 + 1];
            float a2 = Ws[kk][ty * 4 + 2];
            float a3 = Ws[kk][ty * 4 + 3];
            float4 bv = *(const float4*)&Xs[kk][tx * 4];
            acc[0][0] += a0 * bv.x; acc[0][1] += a0 * bv.y; acc[0][2] += a0 * bv.z; acc[0][3] += a0 * bv.w;
            acc[1][0] += a1 * bv.x; acc[1][1] += a1 * bv.y; acc[1][2] += a1 * bv.z; acc[1][3] += a1 * bv.w;
            acc[2][0] += a2 * bv.x; acc[2][1] += a2 * bv.y; acc[2][2] += a2 * bv.z; acc[2][3] += a2 * bv.w;
            acc[3][0] += a3 * bv.x; acc[3][1] += a3 * bv.y; acc[3][2] += a3 * bv.z; acc[3][3] += a3 * bv.w;
        }
        __syncthreads();
    }

#pragma unroll
    for (int i = 0; i < 4; i++) {
        int o = o0 + ty * 4 + i;
        float s  = gam[o] * rsqrtf(var[o] + EPS);
        float sh = beta[o] - mean[o] * s;
        float bi = bias[o];
        size_t base = (size_t)b * O * HW + (size_t)o * HW + p0 + tx * 4;
#pragma unroll
        for (int j = 0; j < 4; j++) {
            float v = fmaxf((acc[i][j] + bi) * s + sh, 0.f);
            if (resid) v += resid[base + j];
            Y[base + j] = v;
        }
    }
}

// ---------------- maxpool 3x3 stride 2 pad 1 : [B,128,64,64] -> [B,128,32,32] ----------------
__global__ void maxpool_kernel(const float* __restrict__ X, float* __restrict__ Y)
{
    int idx = blockIdx.x * 256 + threadIdx.x;
    if (idx >= 8 * 128 * 1024) return;
    int q = idx & 31, p = (idx >> 5) & 31, c = (idx >> 10) & 127, b = idx >> 17;
    const float* Xp = X + ((size_t)(b * 128 + c)) * 4096;
    int r0 = 2 * p - 1, c0 = 2 * q - 1;
    float m = -CUDART_INF_F;
#pragma unroll
    for (int dr = 0; dr < 3; dr++) {
        int r = r0 + dr;
        if (r < 0 || r >= 64) continue;
#pragma unroll
        for (int dc = 0; dc < 3; dc++) {
            int cc = c0 + dc;
            if (cc < 0 || cc >= 64) continue;
            m = fmaxf(m, Xp[r * 64 + cc]);
        }
    }
    Y[idx] = m;
}

// ---------------- fused attention: out = softmax(X1 @ X2) @ X3 ----------------
// Per CTA: batch b, 128 query rows. Stream 8 chunks of 128 keys, online softmax.
// X1 [4096,128] rm (g_x1), X2[c][j]=kv[c*1024+j], X3[j][c]=kv[j*128+c].
// smem: X1s[128][129] (k-major, transposed), MPs[128][128] (Ms then reused for Ps), X3s[128][128]
#define ATTN_SMEM_FLOATS (128 * 129 + 128 * 128 + 128 * 128)
#define ATTN_SMEM_BYTES  (ATTN_SMEM_FLOATS * 4)

__global__ __launch_bounds__(256, 1) void attn_kernel(
    const float* __restrict__ x1, const float* __restrict__ kv, float* __restrict__ out)
{
    extern __shared__ float sm[];
    float* X1s = sm;                 // [128][129]
    float* MPs = sm + 128 * 129;     // [128][128]
    float* X3s = MPs + 128 * 128;    // [128][128]

    const int b  = blockIdx.y;
    const int i0 = blockIdx.x * 128;
    const int tid = threadIdx.x;
    const int tx = tid & 15, ty = tid >> 4;

    const float* X1g = x1 + (size_t)b * 524288 + (size_t)i0 * 128;
    const float* Bg  = kv + (size_t)b * 131072;

    // load X1 tile transposed: X1s[k][i]
#pragma unroll
    for (int l = 0; l < 16; l++) {
        int flat = tid + l * 256;          // float4 index over [128 rows][32 f4]
        int i = flat >> 5, kq = flat & 31;
        float4 v = *(const float4*)(X1g + (size_t)i * 128 + kq * 4);
        int k = kq * 4;
        X1s[(k + 0) * 129 + i] = v.x;
        X1s[(k + 1) * 129 + i] = v.y;
        X1s[(k + 2) * 129 + i] = v.z;
        X1s[(k + 3) * 129 + i] = v.w;
    }

    float Oacc[8][8];
    float mrow[8], lrow[8];
#pragma unroll
    for (int r = 0; r < 8; r++) {
        mrow[r] = -CUDART_INF_F;
        lrow[r] = 0.f;
#pragma unroll
        for (int c = 0; c < 8; c++) Oacc[r][c] = 0.f;
    }

    for (int j0 = 0; j0 < 1024; j0 += 128) {
        __syncthreads();  // protect MPs/X3s from previous-iteration readers (and X1 stores on iter 0)
        // Ms[c][j] = Bg[c*1024 + j0 + j]
#pragma unroll
        for (int l = 0; l < 16; l++) {
            int flat = tid + l * 256;
            int c = flat >> 5, jq = flat & 31;
            *(float4*)&MPs[c * 128 + jq * 4] = *(const float4*)(Bg + (size_t)c * 1024 + j0 + jq * 4);
        }
        // X3s: contiguous block Bg[j0*128 ..]
        {
            const float4* src = (const float4*)(Bg + (size_t)j0 * 128);
#pragma unroll
            for (int l = 0; l < 16; l++)
                ((float4*)X3s)[tid + l * 256] = src[tid + l * 256];
        }
        __syncthreads();

        // gemm1: S[i][j] = sum_k X1s[k][i] * Ms[k][j]
        float S[8][8];
#pragma unroll
        for (int r = 0; r < 8; r++)
#pragma unroll
            for (int c = 0; c < 8; c++) S[r][c] = 0.f;

#pragma unroll 8
        for (int k = 0; k < 128; k++) {
            float a[8];
#pragma unroll
            for (int r = 0; r < 8; r++) a[r] = X1s[k * 129 + ty * 8 + r];
            float4 b0 = *(const float4*)&MPs[k * 128 + tx * 8];
            float4 b1 = *(const float4*)&MPs[k * 128 + tx * 8 + 4];
#pragma unroll
            for (int r = 0; r < 8; r++) {
                S[r][0] += a[r] * b0.x; S[r][1] += a[r] * b0.y;
                S[r][2] += a[r] * b0.z; S[r][3] += a[r] * b0.w;
                S[r][4] += a[r] * b1.x; S[r][5] += a[r] * b1.y;
                S[r][6] += a[r] * b1.z; S[r][7] += a[r] * b1.w;
            }
        }

        // online softmax (row reduction across the 16 tx lanes sharing ty)
#pragma unroll
        for (int r = 0; r < 8; r++) {
            float mx = S[r][0];
#pragma unroll
            for (int c = 1; c < 8; c++) mx = fmaxf(mx, S[r][c]);
            mx = fmaxf(mx, __shfl_xor_sync(0xffffffffu, mx, 1));
            mx = fmaxf(mx, __shfl_xor_sync(0xffffffffu, mx, 2));
            mx = fmaxf(mx, __shfl_xor_sync(0xffffffffu, mx, 4));
            mx = fmaxf(mx, __shfl_xor_sync(0xffffffffu, mx, 8));
            float mn = fmaxf(mrow[r], mx);
            float f  = __expf(mrow[r] - mn);   // 0 when mrow was -inf
            mrow[r] = mn;
            float s = 0.f;
#pragma unroll
            for (int c = 0; c < 8; c++) {
                float p = __expf(S[r][c] - mn);
                S[r][c] = p;
                s += p;
            }
            s += __shfl_xor_sync(0xffffffffu, s, 1);
            s += __shfl_xor_sync(0xffffffffu, s, 2);
            s += __shfl_xor_sync(0xffffffffu, s, 4);
            s += __shfl_xor_sync(0xffffffffu, s, 8);
            lrow[r] = lrow[r] * f + s;
#pragma unroll
            for (int c = 0; c < 8; c++) Oacc[r][c] *= f;
        }

        __syncthreads();  // all warps done reading Ms
        // store P into MPs as [i][j]
#pragma unroll
        for (int r = 0; r < 8; r++) {
            *(float4*)&MPs[(ty * 8 + r) * 128 + tx * 8]     = make_float4(S[r][0], S[r][1], S[r][2], S[r][3]);
            *(float4*)&MPs[(ty * 8 + r) * 128 + tx * 8 + 4] = make_float4(S[r][4], S[r][5], S[r][6], S[r][7]);
        }
        __syncthreads();

        // gemm2: O[i][c] += sum_j P[i][j] * X3s[j][c]
#pragma unroll 8
        for (int j = 0; j < 128; j++) {
            float a[8];
#pragma unroll
            for (int r = 0; r < 8; r++) a[r] = MPs[(ty * 8 + r) * 128 + j];
            float4 b0 = *(const float4*)&X3s[j * 128 + tx * 8];
            float4 b1 = *(const float4*)&X3s[j * 128 + tx * 8 + 4];
#pragma unroll
            for (int r = 0; r < 8; r++) {
                Oacc[r][0] += a[r] * b0.x; Oacc[r][1] += a[r] * b0.y;
                Oacc[r][2] += a[r] * b0.z; Oacc[r][3] += a[r] * b0.w;
                Oacc[r][4] += a[r] * b1.x; Oacc[r][5] += a[r] * b1.y;
                Oacc[r][6] += a[r] * b1.z; Oacc[r][7] += a[r] * b1.w;
            }
        }
    }

    float* og = out + (size_t)b * 524288 + (size_t)i0 * 128;
#pragma unroll
    for (int r = 0; r < 8; r++) {
        float inv = 1.0f / lrow[r];
        *(float4*)(og + (size_t)(ty * 8 + r) * 128 + tx * 8) =
            make_float4(Oacc[r][0] * inv, Oacc[r][1] * inv, Oacc[r][2] * inv, Oacc[r][3] * inv);
        *(float4*)(og + (size_t)(ty * 8 + r) * 128 + tx * 8 + 4) =
            make_float4(Oacc[r][4] * inv, Oacc[r][5] * inv, Oacc[r][6] * inv, Oacc[r][7] * inv);
    }
}

// ---------------- launcher ----------------
extern "C" void kernel_launch(void* const* d_in, const int* in_sizes, int n_in,
                              void* d_out, int out_size)
{
    const float* a       = (const float*)d_in[0];
    const float* conv1_w = (const float*)d_in[1];
    const float* conv1_b = (const float*)d_in[2];
    const float* bn1_g   = (const float*)d_in[3];
    const float* bn1_b   = (const float*)d_in[4];
    const float* bn1_m   = (const float*)d_in[5];
    const float* bn1_v   = (const float*)d_in[6];
    const float* conv2_w = (const float*)d_in[7];
    const float* conv2_b = (const float*)d_in[8];
    const float* bn2_g   = (const float*)d_in[9];
    const float* bn2_b   = (const float*)d_in[10];
    const float* bn2_m   = (const float*)d_in[11];
    const float* bn2_v   = (const float*)d_in[12];
    const float* conv3_w = (const float*)d_in[13];
    const float* conv3_b = (const float*)d_in[14];
    const float* bn3_g   = (const float*)d_in[15];
    const float* bn3_b   = (const float*)d_in[16];
    const float* bn3_m   = (const float*)d_in[17];
    const float* bn3_v   = (const float*)d_in[18];
    float* out = (float*)d_out;

    float *p_x1, *p_y2, *p_x23, *p_attn;
    cudaGetSymbolAddress((void**)&p_x1,   g_x1);
    cudaGetSymbolAddress((void**)&p_y2,   g_y2);
    cudaGetSymbolAddress((void**)&p_x23,  g_x23);
    cudaGetSymbolAddress((void**)&p_attn, g_attn);

    cudaFuncSetAttribute(attn_kernel, cudaFuncAttributeMaxDynamicSharedMemorySize, ATTN_SMEM_BYTES);

    const int HW = 4096;
    dim3 blk(256);

    // conv1: [128,256] x [256,4096] per batch -> g_x1
    conv_bn_relu_kernel<<<dim3(HW / 64, 128 / 64, 8), blk>>>(
        a, conv1_w, conv1_b, bn1_g, bn1_b, bn1_m, bn1_v, nullptr, p_x1, 256, 128, HW);

    // conv2 -> g_y2
    conv_bn_relu_kernel<<<dim3(HW / 64, 128 / 64, 8), blk>>>(
        a, conv2_w, conv2_b, bn2_g, bn2_b, bn2_m, bn2_v, nullptr, p_y2, 256, 128, HW);

    // maxpool -> g_x23
    maxpool_kernel<<<(8 * 128 * 1024) / 256, blk>>>(p_y2, p_x23);

    // attention -> g_attn
    attn_kernel<<<dim3(32, 8), blk, ATTN_SMEM_BYTES>>>(p_x1, p_x23, p_attn);

    // conv3 + residual -> out
    conv_bn_relu_kernel<<<dim3(HW / 64, 256 / 64, 8), blk>>>(
        p_attn, conv3_w, conv3_b, bn3_g, bn3_b, bn3_m, bn3_v, a, out, 128, 256, HW);
}